// round 4
// baseline (speedup 1.0000x reference)
#include <cuda_runtime.h>
#include <math.h>
#include <stdint.h>

// Problem dims
#define HID 512
#define ED  1024
#define SD  128
#define NB  32
#define NS  1024
#define ROWS (NB*NS)          // 32768
#define UVC (2*ED+SD)         // 2176

// ---------------- scratch (device globals; no cudaMalloc allowed) ----------
static __device__ float g_rinv[ROWS];
static __device__ float g_uv[(size_t)ROWS * UVC];    // silu(xn@Wuv+buv): [u | v | base]
static __device__ float g_q [(size_t)ROWS * SD];
static __device__ float g_k [(size_t)ROWS * SD];
static __device__ float g_sc[(size_t)NB * NS * NS];  // relu^2 kernel
static __device__ float g_ukv[(size_t)ROWS * ED];    // u * (kernel @ v)
static __device__ float g_cs[NS * 64];
static __device__ float g_sn[NS * 64];

// ---------------- rope tables -----------------------------------------------
// inv_freq = 10000^(j/64) computed in double then rounded -> matches glibc's
// correctly-rounded powf used by XLA CPU. arg = fl32(n * inv_freq_f32) matches
// XLA's f32 multiply bit-exactly; sin/cos of that exact arg taken in double.
__global__ void rope_table_kernel() {
    int idx = blockIdx.x * blockDim.x + threadIdx.x;   // 65536
    int n = idx >> 6, j = idx & 63;
    double invf_d = pow(10000.0, (double)j / 64.0);
    float invf = (float)invf_d;
    float arg = (float)n * invf;
    g_sn[idx] = (float)sin((double)arg);
    g_cs[idx] = (float)cos((double)arg);
}

// ---------------- row norms --------------------------------------------------
__global__ void norm_kernel(const float* __restrict__ x, const float* __restrict__ g) {
    int row = blockIdx.x;
    int t = threadIdx.x;    // 128 threads, 4 floats each
    float4 v = *(const float4*)(x + (size_t)row * HID + t * 4);
    float ss = v.x*v.x + v.y*v.y + v.z*v.z + v.w*v.w;
    #pragma unroll
    for (int o = 16; o; o >>= 1) ss += __shfl_xor_sync(0xffffffffu, ss, o);
    __shared__ float sred[4];
    if ((t & 31) == 0) sred[t >> 5] = ss;
    __syncthreads();
    if (t == 0) {
        float tot = sred[0] + sred[1] + sred[2] + sred[3];
        float norm = sqrtf(tot) * 0.044194173824159216f;   // * HID^-0.5
        g_rinv[row] = g[0] / fmaxf(norm, 1e-5f);
    }
}

// ---------------- q/k prep: gamma/beta + rope --------------------------------
__global__ void qk_prep_kernel(const float* __restrict__ gamma, const float* __restrict__ beta) {
    int row = blockIdx.x;
    int n = row & (NS - 1);
    int s = threadIdx.x;    // 128
    float base = g_uv[(size_t)row * UVC + 2 * ED + s];
    __shared__ float tb[SD];
    #pragma unroll
    for (int h = 0; h < 2; h++) {
        float tv = base * gamma[h * SD + s] + beta[h * SD + s];
        tb[s] = tv;
        __syncthreads();
        float o;
        if (s < 64) {
            float c = g_cs[n * 64 + s], sn = g_sn[n * 64 + s];
            o = tb[s] * c - tb[s + 64] * sn;
        } else {
            int j = s - 64;
            float c = g_cs[n * 64 + j], sn = g_sn[n * 64 + j];
            o = tb[s] * c + tb[s - 64] * sn;
        }
        float* dst = (h == 0) ? g_q : g_k;
        dst[(size_t)row * SD + s] = o;
        __syncthreads();
    }
}

// ---------------- tiled SGEMM, 128x128x8, 8x8/thread, double-buffered -------
// MODE 0: g_uv = silu((x*rinv) @ Wuv + buv)                 (M=32768,K=512, N=2176)
// MODE 1: g_sc = relu(q@k^T / sqrt(S))^2   per batch (NT)   (M=1024, K=128, N=1024)
// MODE 2: g_ukv = u * (g_sc @ v)           per batch        (M=1024, K=1024,N=1024)
// MODE 3: out  = g_ukv @ Wo + bo + x                        (M=32768,K=1024,N=512)
template<int MODE>
__global__ void __launch_bounds__(256, 2)
gemm128(const float* __restrict__ A_, const float* __restrict__ B_,
        float* __restrict__ C_,
        const float* __restrict__ P0, const float* __restrict__ P1)
{
    constexpr int  K   = (MODE==0)?HID : (MODE==1)?SD : (MODE==2)?NS : ED;
    constexpr int  LDA = (MODE==0)?HID : (MODE==1)?SD : (MODE==2)?NS : ED;
    constexpr int  LDB = (MODE==0)?UVC : (MODE==1)?SD : (MODE==2)?UVC : HID;
    constexpr int  LDC = (MODE==0)?UVC : (MODE==1)?NS : (MODE==2)?ED  : HID;
    constexpr bool BT  = (MODE==1);   // B transposed (NT gemm)

    const float* A = A_;
    const float* B = B_;
    float*       C = C_;
    const float* U = nullptr;
    size_t z = blockIdx.z;
    if constexpr (MODE == 0) {
        C = g_uv;
    } else if constexpr (MODE == 1) {
        A = g_q  + z * (size_t)NS * SD;
        B = g_k  + z * (size_t)NS * SD;
        C = g_sc + z * (size_t)NS * NS;
    } else if constexpr (MODE == 2) {
        A = g_sc + z * (size_t)NS * NS;
        B = g_uv + z * (size_t)NS * UVC + ED;   // v block
        C = g_ukv+ z * (size_t)NS * ED;
        U = g_uv + z * (size_t)NS * UVC;        // u block
    } else {
        A = g_ukv;
    }

    __shared__ float As[2][8][128];
    __shared__ float Bs[2][8][128];

    int t  = threadIdx.x;
    int tx = t & 15, ty = t >> 4;
    int rowBase = blockIdx.y * 128;
    int colBase = blockIdx.x * 128;

    int arow = t >> 1, acol4 = (t & 1) * 4;
    const float* Ap = A + (size_t)(rowBase + arow) * LDA + acol4;
    const float* Bp;
    int brow, bcol4;
    if constexpr (BT) {
        brow = t >> 1; bcol4 = (t & 1) * 4;
        Bp = B + (size_t)(colBase + brow) * LDB + bcol4;
    } else {
        brow = t >> 5; bcol4 = (t & 31) * 4;
        Bp = B + (size_t)brow * LDB + colBase + bcol4;
    }

    float ascale = 1.0f;
    if constexpr (MODE == 0) ascale = g_rinv[rowBase + arow];

    float acc[8][8];
    #pragma unroll
    for (int i = 0; i < 8; i++)
        #pragma unroll
        for (int j = 0; j < 8; j++) acc[i][j] = 0.0f;

    // prefetch first k-slab into registers
    float4 av, bv;
    {
        av = *(const float4*)(Ap + 0);
        if constexpr (MODE == 0) { av.x*=ascale; av.y*=ascale; av.z*=ascale; av.w*=ascale; }
        if constexpr (BT) bv = *(const float4*)(Bp + 0);
        else              bv = *(const float4*)(Bp);
    }

    int buf = 0;
    for (int k0 = 0; k0 < K; k0 += 8) {
        // store current slab into smem[buf]
        As[buf][acol4+0][arow] = av.x; As[buf][acol4+1][arow] = av.y;
        As[buf][acol4+2][arow] = av.z; As[buf][acol4+3][arow] = av.w;
        if constexpr (BT) {
            Bs[buf][bcol4+0][brow] = bv.x; Bs[buf][bcol4+1][brow] = bv.y;
            Bs[buf][bcol4+2][brow] = bv.z; Bs[buf][bcol4+3][brow] = bv.w;
        } else {
            *(float4*)&Bs[buf][brow][bcol4] = bv;
        }
        __syncthreads();

        // prefetch next slab (overlaps with compute below)
        if (k0 + 8 < K) {
            av = *(const float4*)(Ap + k0 + 8);
            if constexpr (MODE == 0) { av.x*=ascale; av.y*=ascale; av.z*=ascale; av.w*=ascale; }
            if constexpr (BT) bv = *(const float4*)(Bp + k0 + 8);
            else              bv = *(const float4*)(Bp + (size_t)(k0 + 8) * LDB);
        }

        #pragma unroll
        for (int kk = 0; kk < 8; kk++) {
            float a[8], b[8];
            *(float4*)&a[0] = *(const float4*)&As[buf][kk][ty*8];
            *(float4*)&a[4] = *(const float4*)&As[buf][kk][ty*8+4];
            *(float4*)&b[0] = *(const float4*)&Bs[buf][kk][tx*8];
            *(float4*)&b[4] = *(const float4*)&Bs[buf][kk][tx*8+4];
            #pragma unroll
            for (int i = 0; i < 8; i++)
                #pragma unroll
                for (int j = 0; j < 8; j++)
                    acc[i][j] = fmaf(a[i], b[j], acc[i][j]);
        }
        buf ^= 1;
        // no second barrier: next iteration writes the other buffer; the
        // sync at the top of iteration i+1 orders everyone past compute(i)
        // before anyone reaches the store of iteration i+2 into this buffer.
    }

    // ---------------- epilogue ----------------
    #pragma unroll
    for (int i = 0; i < 8; i++) {
        int row  = rowBase + ty * 8 + i;
        int col0 = colBase + tx * 8;
        float vals[8];
        #pragma unroll
        for (int j = 0; j < 8; j++) {
            float c = acc[i][j];
            int col = col0 + j;
            if constexpr (MODE == 0) {
                c += P0[col];                              // buv
                float sg = 1.0f / (1.0f + expf(-c));       // silu
                c = c * sg;
            } else if constexpr (MODE == 1) {
                float r = fmaxf(c / 11.313708498984761f, 0.0f);
                c = r * r;
            } else if constexpr (MODE == 2) {
                c *= U[(size_t)row * UVC + col];           // gate by u
            } else {
                c = (c + P0[col]) + P1[(size_t)row * HID + col];   // + bo + shortcut
            }
            vals[j] = c;
        }
        float* cp = C + (size_t)row * LDC + col0;
        *(float4*)(cp + 0) = make_float4(vals[0], vals[1], vals[2], vals[3]);
        *(float4*)(cp + 4) = make_float4(vals[4], vals[5], vals[6], vals[7]);
    }
}

// ---------------- launch -----------------------------------------------------
extern "C" void kernel_launch(void* const* d_in, const int* in_sizes, int n_in,
                              void* d_out, int out_size) {
    const float* x     = (const float*)d_in[0];
    const float* Wuv   = (const float*)d_in[1];
    const float* buv   = (const float*)d_in[2];
    const float* gamma = (const float*)d_in[3];
    const float* beta  = (const float*)d_in[4];
    const float* Wo    = (const float*)d_in[5];
    const float* bo    = (const float*)d_in[6];
    const float* g     = (const float*)d_in[7];
    float* out = (float*)d_out;

    rope_table_kernel<<<256, 256>>>();
    norm_kernel<<<ROWS, 128>>>(x, g);
    gemm128<0><<<dim3(UVC/128, ROWS/128, 1), 256>>>(x, Wuv, nullptr, buv, nullptr);
    qk_prep_kernel<<<ROWS, 128>>>(gamma, beta);
    gemm128<1><<<dim3(NS/128, NS/128, NB), 256>>>(nullptr, nullptr, nullptr, nullptr, nullptr);
    gemm128<2><<<dim3(ED/128, NS/128, NB), 256>>>(nullptr, nullptr, nullptr, nullptr, nullptr);
    gemm128<3><<<dim3(HID/128, ROWS/128, 1), 256>>>(nullptr, Wo, out, bo, x);
}

// round 9
// speedup vs baseline: 1.8452x; 1.8452x over previous
#include <cuda_runtime.h>
#include <cuda_bf16.h>
#include <math.h>
#include <stdint.h>

// ---------------- dims ----------------
#define HID 512
#define ED  1024
#define SD  128
#define NB  32
#define NS  1024
#define ROWS (NB*NS)      // 32768
#define UVC 2176          // 2*ED + SD

typedef __nv_bfloat16 bf16;

// ---------------- device scratch ----------------
static __device__ float g_uv [(size_t)ROWS * UVC];      // silu(xn@Wuv+buv) f32: [u|v|base]
static __device__ bf16  g_xn_hi[(size_t)ROWS * HID];
static __device__ bf16  g_xn_lo[(size_t)ROWS * HID];
static __device__ bf16  g_wuvt_hi[(size_t)UVC * HID];   // Wuv^T [2176][512]
static __device__ bf16  g_wuvt_lo[(size_t)UVC * HID];
static __device__ bf16  g_wot_hi[(size_t)HID * ED];     // Wo^T [512][1024]
static __device__ bf16  g_wot_lo[(size_t)HID * ED];
static __device__ float g_q [(size_t)ROWS * SD];
static __device__ float g_k [(size_t)ROWS * SD];
static __device__ bf16  g_sc_hi[(size_t)NB * NS * NS];
static __device__ bf16  g_sc_lo[(size_t)NB * NS * NS];
static __device__ bf16  g_vt_hi[(size_t)NB * ED * NS];  // v^T per batch [e][m]
static __device__ bf16  g_vt_lo[(size_t)NB * ED * NS];
static __device__ bf16  g_ukv_hi[(size_t)ROWS * ED];
static __device__ bf16  g_ukv_lo[(size_t)ROWS * ED];
static __device__ float g_cs[NS * 64];
static __device__ float g_sn[NS * 64];

// ---------------- PTX helpers (all base sm_80 features; no *_a gating) -------
__device__ __forceinline__ uint32_t smem_u32(const void* p) {
    uint32_t a;
    asm("{ .reg .u64 t; cvta.to.shared.u64 t, %1; cvt.u32.u64 %0, t; }" : "=r"(a) : "l"(p));
    return a;
}
#define CP16(saddr, gptr) \
    asm volatile("cp.async.cg.shared.global [%0], [%1], 16;" :: "r"(saddr), "l"(gptr) : "memory")
#define CP_COMMIT() asm volatile("cp.async.commit_group;" ::: "memory")
#define CP_WAIT1()  asm volatile("cp.async.wait_group 1;" ::: "memory")
#define CP_WAIT0()  asm volatile("cp.async.wait_group 0;" ::: "memory")

__device__ __forceinline__ void ldsm4(uint32_t& r0, uint32_t& r1, uint32_t& r2, uint32_t& r3, uint32_t a) {
    asm volatile("ldmatrix.sync.aligned.m8n8.x4.shared.b16 {%0,%1,%2,%3}, [%4];"
                 : "=r"(r0), "=r"(r1), "=r"(r2), "=r"(r3) : "r"(a));
}
__device__ __forceinline__ void mma16816(float* c, uint32_t a0, uint32_t a1, uint32_t a2, uint32_t a3,
                                         uint32_t b0, uint32_t b1) {
    asm volatile("mma.sync.aligned.m16n8k16.row.col.f32.bf16.bf16.f32 "
                 "{%0,%1,%2,%3}, {%4,%5,%6,%7}, {%8,%9}, {%0,%1,%2,%3};"
                 : "+f"(c[0]), "+f"(c[1]), "+f"(c[2]), "+f"(c[3])
                 : "r"(a0), "r"(a1), "r"(a2), "r"(a3), "r"(b0), "r"(b1));
}

// ---------------- rope tables ----------------
__global__ void rope_table_kernel() {
    int idx = blockIdx.x * blockDim.x + threadIdx.x;
    int n = idx >> 6, j = idx & 63;
    double invf_d = pow(10000.0, (double)j / 64.0);
    float invf = (float)invf_d;
    float arg = (float)n * invf;
    g_sn[idx] = (float)sin((double)arg);
    g_cs[idx] = (float)cos((double)arg);
}

// ---------------- norm + bf16 split of xn ----------------
__global__ void norm_split_kernel(const float* __restrict__ x, const float* __restrict__ g) {
    int row = blockIdx.x;
    int t = threadIdx.x;  // 128
    float4 v = *(const float4*)(x + (size_t)row * HID + t * 4);
    float ss = v.x*v.x + v.y*v.y + v.z*v.z + v.w*v.w;
    #pragma unroll
    for (int o = 16; o; o >>= 1) ss += __shfl_xor_sync(0xffffffffu, ss, o);
    __shared__ float sred[4];
    __shared__ float s_rinv;
    if ((t & 31) == 0) sred[t >> 5] = ss;
    __syncthreads();
    if (t == 0) {
        float tot = sred[0] + sred[1] + sred[2] + sred[3];
        float norm = sqrtf(tot) * 0.044194173824159216f;
        s_rinv = g[0] / fmaxf(norm, 1e-5f);
    }
    __syncthreads();
    float r = s_rinv;
    float xv[4] = {v.x*r, v.y*r, v.z*r, v.w*r};
    size_t base = (size_t)row * HID + t * 4;
    #pragma unroll
    for (int i = 0; i < 4; i++) {
        bf16 h = __float2bfloat16(xv[i]);
        bf16 l = __float2bfloat16(xv[i] - __bfloat162float(h));
        g_xn_hi[base + i] = h;
        g_xn_lo[base + i] = l;
    }
}

// ---------------- transpose + bf16 split ----------------
// WHICH 0: Wuv [512][2176] -> wuvt [2176][512]
// WHICH 1: Wo  [1024][512] -> wot  [512][1024]
// WHICH 2: v from g_uv (+1024) per batch [1024][1024] -> vt [1024][1024]
template<int WHICH>
__global__ void transpose_split_kernel(const float* __restrict__ src_arg) {
    constexpr int C       = (WHICH==0) ? UVC : (WHICH==1) ? HID : NS;
    constexpr int SRC_LD  = (WHICH==0) ? UVC : (WHICH==1) ? HID : UVC;
    constexpr int DST_LD  = (WHICH==0) ? HID : (WHICH==1) ? ED  : NS;
    __shared__ float tile[32][33];
    int z = blockIdx.z;
    const float* src;
    bf16 *dh, *dl;
    if constexpr (WHICH == 0) { src = src_arg; dh = g_wuvt_hi; dl = g_wuvt_lo; }
    else if constexpr (WHICH == 1) { src = src_arg; dh = g_wot_hi; dl = g_wot_lo; }
    else {
        src = g_uv + (size_t)z * NS * UVC + ED;
        dh = g_vt_hi + (size_t)z * ED * NS;
        dl = g_vt_lo + (size_t)z * ED * NS;
    }
    int c0 = blockIdx.x * 32, r0 = blockIdx.y * 32;
    int tx = threadIdx.x, ty = threadIdx.y;   // 32 x 8
    #pragma unroll
    for (int i = ty; i < 32; i += 8) {
        int cc = c0 + tx;
        tile[i][tx] = (cc < C) ? src[(size_t)(r0 + i) * SRC_LD + cc] : 0.0f;
    }
    __syncthreads();
    #pragma unroll
    for (int a = ty; a < 32; a += 8) {
        float v = tile[tx][a];
        bf16 h = __float2bfloat16(v);
        bf16 l = __float2bfloat16(v - __bfloat162float(h));
        size_t o = (size_t)(c0 + a) * DST_LD + r0 + tx;
        dh[o] = h; dl[o] = l;
    }
}

// ---------------- q/k prep ----------------
__global__ void qk_prep_kernel(const float* __restrict__ gamma, const float* __restrict__ beta) {
    int row = blockIdx.x;
    int n = row & (NS - 1);
    int s = threadIdx.x;
    float base = g_uv[(size_t)row * UVC + 2 * ED + s];
    __shared__ float tb[SD];
    #pragma unroll
    for (int h = 0; h < 2; h++) {
        float tv = base * gamma[h * SD + s] + beta[h * SD + s];
        tb[s] = tv;
        __syncthreads();
        float o;
        if (s < 64) {
            float c = g_cs[n * 64 + s], sn = g_sn[n * 64 + s];
            o = tb[s] * c - tb[s + 64] * sn;
        } else {
            int j = s - 64;
            float c = g_cs[n * 64 + j], sn = g_sn[n * 64 + j];
            o = tb[s] * c + tb[s - 64] * sn;
        }
        float* dst = (h == 0) ? g_q : g_k;
        dst[(size_t)row * SD + s] = o;
        __syncthreads();
    }
}

// ---------------- SIMT score GEMM: relu(q@k^T/sqrt(S))^2 -> bf16 hi/lo ------
__global__ void __launch_bounds__(256, 2)
score_gemm_kernel()
{
    size_t z = blockIdx.z;
    const float* A = g_q + z * (size_t)NS * SD;
    const float* B = g_k + z * (size_t)NS * SD;
    bf16* Ch = g_sc_hi + z * (size_t)NS * NS;
    bf16* Cl = g_sc_lo + z * (size_t)NS * NS;

    __shared__ float As[2][8][128];
    __shared__ float Bs[2][8][128];

    int t = threadIdx.x;
    int tx = t & 15, ty = t >> 4;
    int rowBase = blockIdx.y * 128;
    int colBase = blockIdx.x * 128;
    int arow = t >> 1, acol4 = (t & 1) * 4;
    const float* Ap = A + (size_t)(rowBase + arow) * SD + acol4;
    const float* Bp = B + (size_t)(colBase + arow) * SD + acol4;

    float acc[8][8];
    #pragma unroll
    for (int i = 0; i < 8; i++)
        #pragma unroll
        for (int j = 0; j < 8; j++) acc[i][j] = 0.0f;

    float4 av = *(const float4*)(Ap);
    float4 bv = *(const float4*)(Bp);
    int buf = 0;
    for (int k0 = 0; k0 < SD; k0 += 8) {
        As[buf][acol4+0][arow] = av.x; As[buf][acol4+1][arow] = av.y;
        As[buf][acol4+2][arow] = av.z; As[buf][acol4+3][arow] = av.w;
        Bs[buf][acol4+0][arow] = bv.x; Bs[buf][acol4+1][arow] = bv.y;
        Bs[buf][acol4+2][arow] = bv.z; Bs[buf][acol4+3][arow] = bv.w;
        __syncthreads();
        if (k0 + 8 < SD) {
            av = *(const float4*)(Ap + k0 + 8);
            bv = *(const float4*)(Bp + k0 + 8);
        }
        #pragma unroll
        for (int kk = 0; kk < 8; kk++) {
            float a[8], b[8];
            *(float4*)&a[0] = *(const float4*)&As[buf][kk][ty*8];
            *(float4*)&a[4] = *(const float4*)&As[buf][kk][ty*8+4];
            *(float4*)&b[0] = *(const float4*)&Bs[buf][kk][tx*8];
            *(float4*)&b[4] = *(const float4*)&Bs[buf][kk][tx*8+4];
            #pragma unroll
            for (int i = 0; i < 8; i++)
                #pragma unroll
                for (int j = 0; j < 8; j++)
                    acc[i][j] = fmaf(a[i], b[j], acc[i][j]);
        }
        buf ^= 1;
    }

    #pragma unroll
    for (int i = 0; i < 8; i++) {
        int row  = rowBase + ty * 8 + i;
        int col0 = colBase + tx * 8;
        uint32_t ph[4], pl[4];
        #pragma unroll
        for (int jp = 0; jp < 4; jp++) {
            float c0v = acc[i][jp*2], c1v = acc[i][jp*2+1];
            float r0 = fmaxf(c0v / 11.313708498984761f, 0.0f);
            float r1 = fmaxf(c1v / 11.313708498984761f, 0.0f);
            float v0 = r0 * r0, v1 = r1 * r1;
            bf16 h0 = __float2bfloat16(v0); bf16 l0 = __float2bfloat16(v0 - __bfloat162float(h0));
            bf16 h1 = __float2bfloat16(v1); bf16 l1 = __float2bfloat16(v1 - __bfloat162float(h1));
            ph[jp] = (uint32_t)__bfloat16_as_ushort(h0) | ((uint32_t)__bfloat16_as_ushort(h1) << 16);
            pl[jp] = (uint32_t)__bfloat16_as_ushort(l0) | ((uint32_t)__bfloat16_as_ushort(l1) << 16);
        }
        size_t o = (size_t)row * NS + col0;
        *(uint4*)(Ch + o) = make_uint4(ph[0], ph[1], ph[2], ph[3]);
        *(uint4*)(Cl + o) = make_uint4(pl[0], pl[1], pl[2], pl[3]);
    }
}

// ---------------- mma.sync bf16-split GEMM ----------------------------------
// CTA tile 128x128, 8 warps (2m x 4n), warp tile 64x32, k-chunk 32.
// 3-term split: hi*hi + hi*lo + lo*hi, fp32 accumulate.
// MODE 0: g_uv = silu(xn @ Wuv + buv)    K=512
// MODE 2: ukv  = u * (sc @ v) -> bf16    K=1024 (per batch z)
// MODE 3: out  = ukv @ Wo + bo + x       K=1024
#define SMB_AHI 0
#define SMB_ALO 10240
#define SMB_BHI 20480
#define SMB_BLO 30720
#define SMB_BUF 40960
#define SMEM_MMA (2 * SMB_BUF)     // 80 KB

// copy one 128x32-half tile (rows stride ldk halves) into smem (row stride 80B)
__device__ __forceinline__ void cp_chunk(uint32_t sbuf, const bf16* __restrict__ A, int ldk, int k0, int t) {
    #pragma unroll
    for (int i = 0; i < 2; i++) {
        int idx = t + i * 256;
        int r = idx >> 2, c = idx & 3;
        const char* gp = (const char*)(A + (size_t)r * ldk + k0) + c * 16;
        CP16(sbuf + r * 80 + c * 16, gp);
    }
}

template<int MODE>
__global__ void __launch_bounds__(256, 1)
mma_gemm(const float* __restrict__ P0, const float* __restrict__ P1, float* __restrict__ OUT)
{
    constexpr int K  = (MODE == 0) ? HID : 1024;
    constexpr int NC = K / 32;

    extern __shared__ char sm[];
    uint32_t sb = smem_u32(sm);

    int t = threadIdx.x, w = t >> 5, lane = t & 31;
    int rowBase = blockIdx.y * 128;
    int colBase = blockIdx.x * 128;
    size_t z = blockIdx.z;

    const bf16 *Agh, *Agl, *Bgh, *Bgl;
    if constexpr (MODE == 0) {
        Agh = g_xn_hi + (size_t)rowBase * HID;   Agl = g_xn_lo + (size_t)rowBase * HID;
        Bgh = g_wuvt_hi + (size_t)colBase * HID; Bgl = g_wuvt_lo + (size_t)colBase * HID;
    } else if constexpr (MODE == 2) {
        Agh = g_sc_hi + ((size_t)z * NS + rowBase) * NS;  Agl = g_sc_lo + ((size_t)z * NS + rowBase) * NS;
        Bgh = g_vt_hi + ((size_t)z * ED + colBase) * NS;  Bgl = g_vt_lo + ((size_t)z * ED + colBase) * NS;
    } else {
        Agh = g_ukv_hi + (size_t)rowBase * ED;   Agl = g_ukv_lo + (size_t)rowBase * ED;
        Bgh = g_wot_hi + (size_t)colBase * ED;   Bgl = g_wot_lo + (size_t)colBase * ED;
    }

    float acc[4][4][4];
    #pragma unroll
    for (int a = 0; a < 4; a++)
        #pragma unroll
        for (int b = 0; b < 4; b++)
            #pragma unroll
            for (int c = 0; c < 4; c++) acc[a][b][c] = 0.0f;

    // issue chunk 0
    {
        uint32_t s0 = sb;
        cp_chunk(s0 + SMB_AHI, Agh, K, 0, t);
        cp_chunk(s0 + SMB_ALO, Agl, K, 0, t);
        cp_chunk(s0 + SMB_BHI, Bgh, K, 0, t);
        cp_chunk(s0 + SMB_BLO, Bgl, K, 0, t);
        CP_COMMIT();
    }

    int wm = w & 1, wn = w >> 1;
    int buf = 0;
    for (int c = 0; c < NC; c++) {
        if (c + 1 < NC) {
            uint32_t sn = sb + (buf ^ 1) * SMB_BUF;
            int k0 = (c + 1) * 32;
            cp_chunk(sn + SMB_AHI, Agh, K, k0, t);
            cp_chunk(sn + SMB_ALO, Agl, K, k0, t);
            cp_chunk(sn + SMB_BHI, Bgh, K, k0, t);
            cp_chunk(sn + SMB_BLO, Bgl, K, k0, t);
            CP_COMMIT();
            CP_WAIT1();
        } else {
            CP_WAIT0();
        }
        __syncthreads();

        uint32_t sc = sb + buf * SMB_BUF;
        #pragma unroll
        for (int ks = 0; ks < 2; ks++) {
            int kl = ks * 16;
            // A fragments: row = wm*64 + mt*16 + (lane&15), col = kl + (lane>>4)*8
            uint32_t ah[4][4], al[4][4];
            #pragma unroll
            for (int mt = 0; mt < 4; mt++) {
                int r = wm * 64 + mt * 16 + (lane & 15);
                int cc = kl + (lane >> 4) * 8;
                uint32_t off = (uint32_t)(r * 80 + cc * 2);
                ldsm4(ah[mt][0], ah[mt][1], ah[mt][2], ah[mt][3], sc + SMB_AHI + off);
                ldsm4(al[mt][0], al[mt][1], al[mt][2], al[mt][3], sc + SMB_ALO + off);
            }
            // B fragments: x4 covers 2 n-tiles: lane group g=lane>>3:
            //   nt = base + (g>>1), col = kl + (g&1)*8, row = n-tile row + (lane&7)
            uint32_t bh[4][2], bl[4][2];
            #pragma unroll
            for (int np = 0; np < 2; np++) {
                int g = lane >> 3;
                int r = wn * 32 + (np * 2 + (g >> 1)) * 8 + (lane & 7);
                int cc = kl + (g & 1) * 8;
                uint32_t off = (uint32_t)(r * 80 + cc * 2);
                ldsm4(bh[np*2][0], bh[np*2][1], bh[np*2+1][0], bh[np*2+1][1], sc + SMB_BHI + off);
                ldsm4(bl[np*2][0], bl[np*2][1], bl[np*2+1][0], bl[np*2+1][1], sc + SMB_BLO + off);
            }
            #pragma unroll
            for (int mt = 0; mt < 4; mt++)
                #pragma unroll
                for (int nt = 0; nt < 4; nt++) {
                    mma16816(acc[mt][nt], ah[mt][0], ah[mt][1], ah[mt][2], ah[mt][3], bh[nt][0], bh[nt][1]);
                    mma16816(acc[mt][nt], ah[mt][0], ah[mt][1], ah[mt][2], ah[mt][3], bl[nt][0], bl[nt][1]);
                    mma16816(acc[mt][nt], al[mt][0], al[mt][1], al[mt][2], al[mt][3], bh[nt][0], bh[nt][1]);
                }
        }
        __syncthreads();   // all reads of buf done before it is refilled next iter
        buf ^= 1;
    }

    // ---------------- epilogue ----------------
    int quad = lane >> 2, qi = lane & 3;
    #pragma unroll
    for (int mt = 0; mt < 4; mt++) {
        #pragma unroll
        for (int rr = 0; rr < 2; rr++) {
            size_t row = (size_t)rowBase + wm * 64 + mt * 16 + quad + rr * 8;
            #pragma unroll
            for (int nt = 0; nt < 4; nt++) {
                int col = colBase + wn * 32 + nt * 8 + qi * 2;
                float v0 = acc[mt][nt][rr * 2 + 0];
                float v1 = acc[mt][nt][rr * 2 + 1];
                if constexpr (MODE == 0) {
                    v0 += P0[col];   v1 += P0[col + 1];
                    v0 = v0 / (1.0f + expf(-v0));
                    v1 = v1 / (1.0f + expf(-v1));
                    *(float2*)(g_uv + row * UVC + col) = make_float2(v0, v1);
                } else if constexpr (MODE == 2) {
                    size_t grow = (size_t)z * NS + row;
                    const float* up = g_uv + grow * UVC + col;
                    v0 *= up[0]; v1 *= up[1];
                    bf16 h0 = __float2bfloat16(v0); bf16 l0 = __float2bfloat16(v0 - __bfloat162float(h0));
                    bf16 h1 = __float2bfloat16(v1); bf16 l1 = __float2bfloat16(v1 - __bfloat162float(h1));
                    uint32_t ph = (uint32_t)__bfloat16_as_ushort(h0) | ((uint32_t)__bfloat16_as_ushort(h1) << 16);
                    uint32_t pl = (uint32_t)__bfloat16_as_ushort(l0) | ((uint32_t)__bfloat16_as_ushort(l1) << 16);
                    size_t o = grow * ED + col;
                    *(uint32_t*)(g_ukv_hi + o) = ph;
                    *(uint32_t*)(g_ukv_lo + o) = pl;
                } else {
                    const float* xp = P1 + row * HID + col;
                    v0 = (v0 + P0[col])     + xp[0];
                    v1 = (v1 + P0[col + 1]) + xp[1];
                    *(float2*)(OUT + row * HID + col) = make_float2(v0, v1);
                }
            }
        }
    }
}

// ---------------- launch ----------------
extern "C" void kernel_launch(void* const* d_in, const int* in_sizes, int n_in,
                              void* d_out, int out_size) {
    const float* x     = (const float*)d_in[0];
    const float* Wuv   = (const float*)d_in[1];
    const float* buv   = (const float*)d_in[2];
    const float* gamma = (const float*)d_in[3];
    const float* beta  = (const float*)d_in[4];
    const float* Wo    = (const float*)d_in[5];
    const float* bo    = (const float*)d_in[6];
    const float* g     = (const float*)d_in[7];
    float* out = (float*)d_out;

    cudaFuncSetAttribute(mma_gemm<0>, cudaFuncAttributeMaxDynamicSharedMemorySize, SMEM_MMA);
    cudaFuncSetAttribute(mma_gemm<2>, cudaFuncAttributeMaxDynamicSharedMemorySize, SMEM_MMA);
    cudaFuncSetAttribute(mma_gemm<3>, cudaFuncAttributeMaxDynamicSharedMemorySize, SMEM_MMA);

    rope_table_kernel<<<256, 256>>>();
    norm_split_kernel<<<ROWS, 128>>>(x, g);
    transpose_split_kernel<0><<<dim3(UVC/32, HID/32, 1), dim3(32, 8)>>>(Wuv);
    transpose_split_kernel<1><<<dim3(HID/32, ED/32, 1), dim3(32, 8)>>>(Wo);
    mma_gemm<0><<<dim3(UVC/128, ROWS/128, 1), 256, SMEM_MMA>>>(buv, nullptr, nullptr);
    qk_prep_kernel<<<ROWS, 128>>>(gamma, beta);
    score_gemm_kernel<<<dim3(NS/128, NS/128, NB), 256>>>();
    transpose_split_kernel<2><<<dim3(NS/32, NS/32, NB), dim3(32, 8)>>>(nullptr);
    mma_gemm<2><<<dim3(ED/128, NS/128, NB), 256, SMEM_MMA>>>(nullptr, nullptr, nullptr);
    mma_gemm<3><<<dim3(HID/128, ROWS/128, 1), 256, SMEM_MMA>>>(bo, x, out);
}

// round 12
// speedup vs baseline: 2.0064x; 1.0874x over previous
#include <cuda_runtime.h>
#include <cuda_bf16.h>
#include <math.h>
#include <stdint.h>

// ---------------- dims ----------------
#define HID 512
#define ED  1024
#define SD  128
#define NB  32
#define NS  1024
#define ROWS (NB*NS)      // 32768
#define UVC 2176          // 2*ED + SD

typedef __nv_bfloat16 bf16;

// ---------------- device scratch ----------------
static __device__ bf16  g_xn_hi[(size_t)ROWS * HID];
static __device__ bf16  g_xn_lo[(size_t)ROWS * HID];
static __device__ bf16  g_wuv_hi[(size_t)HID * UVC];    // Wuv natural [512][2176]
static __device__ bf16  g_wuv_lo[(size_t)HID * UVC];
static __device__ bf16  g_wo_hi[(size_t)ED * HID];      // Wo natural [1024][512]
static __device__ bf16  g_wo_lo[(size_t)ED * HID];
static __device__ float g_u   [(size_t)ROWS * ED];      // u (f32 gate)
static __device__ bf16  g_v_hi[(size_t)ROWS * ED];      // v split, natural [m][e]
static __device__ bf16  g_v_lo[(size_t)ROWS * ED];
static __device__ float g_base[(size_t)ROWS * SD];      // base (pre gamma/beta/rope)
static __device__ bf16  g_q_hi[(size_t)ROWS * SD];
static __device__ bf16  g_q_lo[(size_t)ROWS * SD];
static __device__ bf16  g_k_hi[(size_t)ROWS * SD];
static __device__ bf16  g_k_lo[(size_t)ROWS * SD];
static __device__ bf16  g_sc_hi[(size_t)NB * NS * NS];  // scores split [n][m]
static __device__ bf16  g_sc_lo[(size_t)NB * NS * NS];
static __device__ bf16  g_ukv_hi[(size_t)ROWS * ED];
static __device__ bf16  g_ukv_lo[(size_t)ROWS * ED];
static __device__ float g_cs[NS * 64];
static __device__ float g_sn[NS * 64];

// ---------------- PTX helpers (base sm_80/75 features only) ------------------
__device__ __forceinline__ uint32_t smem_u32(const void* p) {
    uint32_t a;
    asm("{ .reg .u64 t; cvta.to.shared.u64 t, %1; cvt.u32.u64 %0, t; }" : "=r"(a) : "l"(p));
    return a;
}
#define CP16(saddr, gptr) \
    asm volatile("cp.async.cg.shared.global [%0], [%1], 16;" :: "r"(saddr), "l"(gptr) : "memory")
#define CP_COMMIT() asm volatile("cp.async.commit_group;" ::: "memory")
#define CP_WAIT2()  asm volatile("cp.async.wait_group 2;" ::: "memory")
#define CP_WAIT1()  asm volatile("cp.async.wait_group 1;" ::: "memory")
#define CP_WAIT0()  asm volatile("cp.async.wait_group 0;" ::: "memory")

__device__ __forceinline__ void ldsm4(uint32_t& r0, uint32_t& r1, uint32_t& r2, uint32_t& r3, uint32_t a) {
    asm volatile("ldmatrix.sync.aligned.m8n8.x4.shared.b16 {%0,%1,%2,%3}, [%4];"
                 : "=r"(r0), "=r"(r1), "=r"(r2), "=r"(r3) : "r"(a));
}
__device__ __forceinline__ void ldsm4t(uint32_t& r0, uint32_t& r1, uint32_t& r2, uint32_t& r3, uint32_t a) {
    asm volatile("ldmatrix.sync.aligned.m8n8.x4.trans.shared.b16 {%0,%1,%2,%3}, [%4];"
                 : "=r"(r0), "=r"(r1), "=r"(r2), "=r"(r3) : "r"(a));
}
__device__ __forceinline__ void mma16816(float* c, uint32_t a0, uint32_t a1, uint32_t a2, uint32_t a3,
                                         uint32_t b0, uint32_t b1) {
    asm volatile("mma.sync.aligned.m16n8k16.row.col.f32.bf16.bf16.f32 "
                 "{%0,%1,%2,%3}, {%4,%5,%6,%7}, {%8,%9}, {%0,%1,%2,%3};"
                 : "+f"(c[0]), "+f"(c[1]), "+f"(c[2]), "+f"(c[3])
                 : "r"(a0), "r"(a1), "r"(a2), "r"(a3), "r"(b0), "r"(b1));
}
__device__ __forceinline__ uint32_t pack_split(float v0, float v1, uint32_t& lo_out) {
    bf16 h0 = __float2bfloat16(v0); bf16 l0 = __float2bfloat16(v0 - __bfloat162float(h0));
    bf16 h1 = __float2bfloat16(v1); bf16 l1 = __float2bfloat16(v1 - __bfloat162float(h1));
    lo_out = (uint32_t)__bfloat16_as_ushort(l0) | ((uint32_t)__bfloat16_as_ushort(l1) << 16);
    return (uint32_t)__bfloat16_as_ushort(h0) | ((uint32_t)__bfloat16_as_ushort(h1) << 16);
}

// ---------------- rope tables ----------------
__global__ void rope_table_kernel() {
    int idx = blockIdx.x * blockDim.x + threadIdx.x;
    int n = idx >> 6, j = idx & 63;
    double invf_d = pow(10000.0, (double)j / 64.0);
    float invf = (float)invf_d;
    float arg = (float)n * invf;
    g_sn[idx] = (float)sin((double)arg);
    g_cs[idx] = (float)cos((double)arg);
}

// ---------------- norm + bf16 split of xn ----------------
__global__ void norm_split_kernel(const float* __restrict__ x, const float* __restrict__ g) {
    int row = blockIdx.x;
    int t = threadIdx.x;  // 128
    float4 v = *(const float4*)(x + (size_t)row * HID + t * 4);
    float ss = v.x*v.x + v.y*v.y + v.z*v.z + v.w*v.w;
    #pragma unroll
    for (int o = 16; o; o >>= 1) ss += __shfl_xor_sync(0xffffffffu, ss, o);
    __shared__ float sred[4];
    __shared__ float s_rinv;
    if ((t & 31) == 0) sred[t >> 5] = ss;
    __syncthreads();
    if (t == 0) {
        float tot = sred[0] + sred[1] + sred[2] + sred[3];
        float norm = sqrtf(tot) * 0.044194173824159216f;
        s_rinv = g[0] / fmaxf(norm, 1e-5f);
    }
    __syncthreads();
    float r = s_rinv;
    float xv[4] = {v.x*r, v.y*r, v.z*r, v.w*r};
    size_t base = (size_t)row * HID + t * 4;
    #pragma unroll
    for (int i = 0; i < 4; i++) {
        bf16 h = __float2bfloat16(xv[i]);
        bf16 l = __float2bfloat16(xv[i] - __bfloat162float(h));
        g_xn_hi[base + i] = h;
        g_xn_lo[base + i] = l;
    }
}

// ---------------- elementwise weight split (no transpose) --------------------
__global__ void wsplit_kernel(const float* __restrict__ src, bf16* __restrict__ dh,
                              bf16* __restrict__ dl, int n4) {
    int i = blockIdx.x * blockDim.x + threadIdx.x;
    if (i >= n4) return;
    float4 v = *(const float4*)(src + (size_t)i * 4);
    uint32_t l0, l1;
    uint32_t h0 = pack_split(v.x, v.y, l0);
    uint32_t h1 = pack_split(v.z, v.w, l1);
    *(uint2*)(dh + (size_t)i * 4) = make_uint2(h0, h1);
    *(uint2*)(dl + (size_t)i * 4) = make_uint2(l0, l1);
}

// ---------------- q/k prep: gamma/beta + rope -> bf16 hi/lo ------------------
__global__ void qk_prep_kernel(const float* __restrict__ gamma, const float* __restrict__ beta) {
    int row = blockIdx.x;
    int n = row & (NS - 1);
    int s = threadIdx.x;    // 128
    float base = g_base[(size_t)row * SD + s];
    __shared__ float tb[SD];
    #pragma unroll
    for (int h = 0; h < 2; h++) {
        float tv = base * gamma[h * SD + s] + beta[h * SD + s];
        tb[s] = tv;
        __syncthreads();
        float o;
        if (s < 64) {
            float c = g_cs[n * 64 + s], sn = g_sn[n * 64 + s];
            o = tb[s] * c - tb[s + 64] * sn;
        } else {
            int j = s - 64;
            float c = g_cs[n * 64 + j], sn = g_sn[n * 64 + j];
            o = tb[s] * c + tb[s - 64] * sn;
        }
        bf16 hh = __float2bfloat16(o);
        bf16 ll = __float2bfloat16(o - __bfloat162float(hh));
        size_t off = (size_t)row * SD + s;
        if (h == 0) { g_q_hi[off] = hh; g_q_lo[off] = ll; }
        else        { g_k_hi[off] = hh; g_k_lo[off] = ll; }
        __syncthreads();
    }
}

// ---------------- unified mma.sync bf16-split GEMM ---------------------------
// CTA tile 128x128, 8 warps (2m x 4n), warp tile 64x32, k-chunk 32, 3-stage.
// MODE 0: [u|v|base] = silu(xn @ Wuv + buv)   K=512,  B=[k][n] trans
// MODE 1: sc = relu(q@k^T/sqrt(S))^2          K=128,  B=[n][k] non-trans
// MODE 2: ukv = u * (sc @ v)                  K=1024, B=[k][n] trans
// MODE 3: out = ukv @ Wo + bo + x             K=1024, B=[k][n] trans
#define SA_HI 0
#define SA_LO 10240
#define SB_HI 20480
// trans B tile: 32 rows x (256B data + 16B pad) = 8704 per half
#define BT_ROW 272

template<bool BT>
struct BufCfg;
template<> struct BufCfg<true>  { static const int SB_LO = 20480 + 8704;  static const int SZ = 37888; };
template<> struct BufCfg<false> { static const int SB_LO = 30720;         static const int SZ = 40960; };

// A-style copy: 128 rows x 32 k bf16, smem row stride 80B
__device__ __forceinline__ void cp_a(uint32_t sbuf, const bf16* __restrict__ A, int ldk, int k0, int t) {
    #pragma unroll
    for (int i = 0; i < 2; i++) {
        int idx = t + i * 256;
        int r = idx >> 2, c = idx & 3;
        const char* gp = (const char*)(A + (size_t)r * ldk + k0) + c * 16;
        CP16(sbuf + r * 80 + c * 16, gp);
    }
}
// trans-B copy: 32 k-rows x 128 n bf16, smem row stride 272B
__device__ __forceinline__ void cp_bt(uint32_t sbuf, const bf16* __restrict__ B, int ldn, int k0, int t) {
    #pragma unroll
    for (int i = 0; i < 2; i++) {
        int idx = t + i * 256;
        int r = idx >> 4, c = idx & 15;
        const char* gp = (const char*)(B + (size_t)(k0 + r) * ldn) + c * 16;
        CP16(sbuf + r * BT_ROW + c * 16, gp);
    }
}

template<int MODE>
__global__ void __launch_bounds__(256, 1)
mma_gemm(const float* __restrict__ P0, const float* __restrict__ P1, float* __restrict__ OUT)
{
    constexpr int  K  = (MODE == 0) ? HID : (MODE == 1) ? SD : 1024;
    constexpr int  NC = K / 32;
    constexpr bool BT = (MODE != 1);
    constexpr int  SB_LO = BufCfg<BT>::SB_LO;
    constexpr int  BUFSZ = BufCfg<BT>::SZ;
    constexpr int  LDB = (MODE == 0) ? UVC : (MODE == 1) ? SD : (MODE == 2) ? ED : HID;

    extern __shared__ char sm[];
    uint32_t sb = smem_u32(sm);

    int t = threadIdx.x, w = t >> 5, lane = t & 31;
    int rowBase = blockIdx.y * 128;
    int colBase = blockIdx.x * 128;
    size_t z = blockIdx.z;

    const bf16 *Agh, *Agl, *Bgh, *Bgl;
    int lda;
    if constexpr (MODE == 0) {
        lda = HID;
        Agh = g_xn_hi + (size_t)rowBase * HID;  Agl = g_xn_lo + (size_t)rowBase * HID;
        Bgh = g_wuv_hi + colBase;               Bgl = g_wuv_lo + colBase;
    } else if constexpr (MODE == 1) {
        lda = SD;
        Agh = g_q_hi + ((size_t)z * NS + rowBase) * SD;  Agl = g_q_lo + ((size_t)z * NS + rowBase) * SD;
        Bgh = g_k_hi + ((size_t)z * NS + colBase) * SD;  Bgl = g_k_lo + ((size_t)z * NS + colBase) * SD;
    } else if constexpr (MODE == 2) {
        lda = NS;
        Agh = g_sc_hi + ((size_t)z * NS + rowBase) * NS;  Agl = g_sc_lo + ((size_t)z * NS + rowBase) * NS;
        Bgh = g_v_hi + (size_t)z * NS * ED + colBase;     Bgl = g_v_lo + (size_t)z * NS * ED + colBase;
    } else {
        lda = ED;
        Agh = g_ukv_hi + (size_t)rowBase * ED;  Agl = g_ukv_lo + (size_t)rowBase * ED;
        Bgh = g_wo_hi + colBase;                Bgl = g_wo_lo + colBase;
    }

    float acc[4][4][4];
    #pragma unroll
    for (int a = 0; a < 4; a++)
        #pragma unroll
        for (int b = 0; b < 4; b++)
            #pragma unroll
            for (int c = 0; c < 4; c++) acc[a][b][c] = 0.0f;

    auto issue = [&](int c) {
        uint32_t sn = sb + (c % 3) * BUFSZ;
        int k0 = c * 32;
        cp_a(sn + SA_HI, Agh, lda, k0, t);
        cp_a(sn + SA_LO, Agl, lda, k0, t);
        if constexpr (BT) {
            cp_bt(sn + SB_HI, Bgh, LDB, k0, t);
            cp_bt(sn + SB_LO, Bgl, LDB, k0, t);
        } else {
            cp_a(sn + SB_HI, Bgh, LDB, k0, t);
            cp_a(sn + SB_LO, Bgl, LDB, k0, t);
        }
        CP_COMMIT();
    };
    issue(0);
    issue(1);

    int wm = w & 1, wn = w >> 1;
    for (int c = 0; c < NC; c++) {
        if (c + 2 < NC) { issue(c + 2); CP_WAIT2(); }
        else if (c + 1 < NC) CP_WAIT1();
        else CP_WAIT0();
        __syncthreads();

        uint32_t sc = sb + (c % 3) * BUFSZ;
        #pragma unroll
        for (int ks = 0; ks < 2; ks++) {
            int kl = ks * 16;
            uint32_t ah[4][4], al[4][4];
            #pragma unroll
            for (int mt = 0; mt < 4; mt++) {
                int r = wm * 64 + mt * 16 + (lane & 15);
                int cc = kl + (lane >> 4) * 8;
                uint32_t off = (uint32_t)(r * 80 + cc * 2);
                ldsm4(ah[mt][0], ah[mt][1], ah[mt][2], ah[mt][3], sc + SA_HI + off);
                ldsm4(al[mt][0], al[mt][1], al[mt][2], al[mt][3], sc + SA_LO + off);
            }
            uint32_t bh[4][2], bl[4][2];
            #pragma unroll
            for (int np = 0; np < 2; np++) {
                if constexpr (BT) {
                    // trans: addresses point at k-rows; matrix g=(lane>>3): (n-half g>>1, k-half g&1)
                    int g = lane >> 3;
                    int r = kl + (g & 1) * 8 + (lane & 7);
                    int cc = wn * 32 + (np * 2 + (g >> 1)) * 8;
                    uint32_t off = (uint32_t)(r * BT_ROW + cc * 2);
                    ldsm4t(bh[np*2][0], bh[np*2][1], bh[np*2+1][0], bh[np*2+1][1], sc + SB_HI + off);
                    ldsm4t(bl[np*2][0], bl[np*2][1], bl[np*2+1][0], bl[np*2+1][1], sc + SB_LO + off);
                } else {
                    int g = lane >> 3;
                    int r = wn * 32 + (np * 2 + (g >> 1)) * 8 + (lane & 7);
                    int cc = kl + (g & 1) * 8;
                    uint32_t off = (uint32_t)(r * 80 + cc * 2);
                    ldsm4(bh[np*2][0], bh[np*2][1], bh[np*2+1][0], bh[np*2+1][1], sc + SB_HI + off);
                    ldsm4(bl[np*2][0], bl[np*2][1], bl[np*2+1][0], bl[np*2+1][1], sc + SB_LO + off);
                }
            }
            #pragma unroll
            for (int mt = 0; mt < 4; mt++)
                #pragma unroll
                for (int nt = 0; nt < 4; nt++) {
                    mma16816(acc[mt][nt], ah[mt][0], ah[mt][1], ah[mt][2], ah[mt][3], bh[nt][0], bh[nt][1]);
                    mma16816(acc[mt][nt], ah[mt][0], ah[mt][1], ah[mt][2], ah[mt][3], bl[nt][0], bl[nt][1]);
                    mma16816(acc[mt][nt], al[mt][0], al[mt][1], al[mt][2], al[mt][3], bh[nt][0], bh[nt][1]);
                }
        }
        __syncthreads();
    }

    // ---------------- epilogue ----------------
    int quad = lane >> 2, qi = lane & 3;
    #pragma unroll
    for (int mt = 0; mt < 4; mt++) {
        #pragma unroll
        for (int rr = 0; rr < 2; rr++) {
            size_t row = (size_t)rowBase + wm * 64 + mt * 16 + quad + rr * 8;
            #pragma unroll
            for (int nt = 0; nt < 4; nt++) {
                int col = colBase + wn * 32 + nt * 8 + qi * 2;
                float v0 = acc[mt][nt][rr * 2 + 0];
                float v1 = acc[mt][nt][rr * 2 + 1];
                if constexpr (MODE == 0) {
                    v0 += P0[col];   v1 += P0[col + 1];
                    v0 = v0 / (1.0f + expf(-v0));
                    v1 = v1 / (1.0f + expf(-v1));
                    if (col < ED) {
                        *(float2*)(g_u + row * ED + col) = make_float2(v0, v1);
                    } else if (col < 2 * ED) {
                        uint32_t lo;
                        uint32_t hi = pack_split(v0, v1, lo);
                        size_t o = row * ED + (col - ED);
                        *(uint32_t*)(g_v_hi + o) = hi;
                        *(uint32_t*)(g_v_lo + o) = lo;
                    } else {
                        *(float2*)(g_base + row * SD + (col - 2 * ED)) = make_float2(v0, v1);
                    }
                } else if constexpr (MODE == 1) {
                    float r0 = fmaxf(v0 / 11.313708498984761f, 0.0f);
                    float r1 = fmaxf(v1 / 11.313708498984761f, 0.0f);
                    v0 = r0 * r0; v1 = r1 * r1;
                    uint32_t lo;
                    uint32_t hi = pack_split(v0, v1, lo);
                    size_t o = ((size_t)z * NS + row) * NS + col;
                    *(uint32_t*)(g_sc_hi + o) = hi;
                    *(uint32_t*)(g_sc_lo + o) = lo;
                } else if constexpr (MODE == 2) {
                    size_t grow = (size_t)z * NS + row;
                    const float* up = g_u + grow * ED + col;
                    v0 *= up[0]; v1 *= up[1];
                    uint32_t lo;
                    uint32_t hi = pack_split(v0, v1, lo);
                    size_t o = grow * ED + col;
                    *(uint32_t*)(g_ukv_hi + o) = hi;
                    *(uint32_t*)(g_ukv_lo + o) = lo;
                } else {
                    const float* xp = P1 + row * HID + col;
                    v0 = (v0 + P0[col])     + xp[0];
                    v1 = (v1 + P0[col + 1]) + xp[1];
                    *(float2*)(OUT + row * HID + col) = make_float2(v0, v1);
                }
            }
        }
    }
}

// ---------------- launch ----------------
extern "C" void kernel_launch(void* const* d_in, const int* in_sizes, int n_in,
                              void* d_out, int out_size) {
    const float* x     = (const float*)d_in[0];
    const float* Wuv   = (const float*)d_in[1];
    const float* buv   = (const float*)d_in[2];
    const float* gamma = (const float*)d_in[3];
    const float* beta  = (const float*)d_in[4];
    const float* Wo    = (const float*)d_in[5];
    const float* bo    = (const float*)d_in[6];
    const float* g     = (const float*)d_in[7];
    float* out = (float*)d_out;

    const int SM_T = 3 * BufCfg<true>::SZ;    // 113664
    const int SM_N = 3 * BufCfg<false>::SZ;   // 122880
    cudaFuncSetAttribute(mma_gemm<0>, cudaFuncAttributeMaxDynamicSharedMemorySize, SM_T);
    cudaFuncSetAttribute(mma_gemm<1>, cudaFuncAttributeMaxDynamicSharedMemorySize, SM_N);
    cudaFuncSetAttribute(mma_gemm<2>, cudaFuncAttributeMaxDynamicSharedMemorySize, SM_T);
    cudaFuncSetAttribute(mma_gemm<3>, cudaFuncAttributeMaxDynamicSharedMemorySize, SM_T);

    bf16 *wuv_hi, *wuv_lo, *wo_hi, *wo_lo;
    cudaGetSymbolAddress((void**)&wuv_hi, g_wuv_hi);
    cudaGetSymbolAddress((void**)&wuv_lo, g_wuv_lo);
    cudaGetSymbolAddress((void**)&wo_hi, g_wo_hi);
    cudaGetSymbolAddress((void**)&wo_lo, g_wo_lo);

    rope_table_kernel<<<256, 256>>>();
    norm_split_kernel<<<ROWS, 128>>>(x, g);
    wsplit_kernel<<<(HID * UVC / 4 + 255) / 256, 256>>>(Wuv, wuv_hi, wuv_lo, HID * UVC / 4);
    wsplit_kernel<<<(ED * HID / 4 + 255) / 256, 256>>>(Wo, wo_hi, wo_lo, ED * HID / 4);
    mma_gemm<0><<<dim3(UVC/128, ROWS/128, 1), 256, SM_T>>>(buv, nullptr, nullptr);
    qk_prep_kernel<<<ROWS, 128>>>(gamma, beta);
    mma_gemm<1><<<dim3(NS/128, NS/128, NB), 256, SM_N>>>(nullptr, nullptr, nullptr);
    mma_gemm<2><<<dim3(ED/128, NS/128, NB), 256, SM_T>>>(nullptr, nullptr, nullptr);
    mma_gemm<3><<<dim3(HID/128, ROWS/128, 1), 256, SM_T>>>(bo, x, out);
}